// round 1
// baseline (speedup 1.0000x reference)
#include <cuda_runtime.h>
#include <cuda_bf16.h>

// Problem constants (fixed by the dataset)
#define BB 16
#define TT 32641
#define EE 128
#define LL (TT + EE - 1)          // 32768 groups (power of two)
#define RR 64                      // rows per tile
#define TILES ((TT + RR - 1) / RR) // 511

// Scratch: per-(batch, group) partial sums. 2 x 2 MB.
__device__ float g_S1[BB * LL];
__device__ float g_S2[BB * LL];

// ---------------------------------------------------------------------------
// Kernel 0: zero scratch + output scalar
// ---------------------------------------------------------------------------
__global__ void tcl_init_kernel(float* __restrict__ out) {
    int idx = blockIdx.x * blockDim.x + threadIdx.x;
    if (idx < BB * LL) {
        g_S1[idx] = 0.0f;
        g_S2[idx] = 0.0f;
    }
    if (idx == 0) out[0] = 0.0f;
}

// ---------------------------------------------------------------------------
// Kernel 1: per-tile anti-diagonal partial sums
// Block = 256 threads. Tile = RR rows x 128 cols staged in smem (pitch 129).
// Thread d (< RR+127) owns diagonal t = r0 + d within this tile and reads
// smem[i*129 + (d-i)] = smem[i*128 + d]  -> bank = d mod 32, conflict-free.
// ---------------------------------------------------------------------------
__global__ void tcl_diag_kernel(const float* __restrict__ x) {
    __shared__ float tile[RR * 129];

    const int b  = blockIdx.y;
    const int r0 = blockIdx.x * RR;
    const int tid = threadIdx.x;
    const float* xb = x + (size_t)b * TT * EE;

    // Coalesced float4 load of RR x 128 floats (rows >= TT zero-filled).
    // RR*EE/4 = 2048 float4 across 256 threads -> 8 each.
    #pragma unroll
    for (int v = tid; v < RR * EE / 4; v += 256) {
        int row  = v >> 5;          // / (EE/4)
        int colv = v & 31;          // % (EE/4)
        float4 val = make_float4(0.f, 0.f, 0.f, 0.f);
        int gr = r0 + row;
        if (gr < TT) {
            val = __ldg((const float4*)(xb + (size_t)gr * EE) + colv);
        }
        int base = row * 129 + colv * 4;
        tile[base + 0] = val.x;
        tile[base + 1] = val.y;
        tile[base + 2] = val.z;
        tile[base + 3] = val.w;
    }
    __syncthreads();

    const int d = tid;
    const int D = RR + EE - 1;      // 191 diagonals per tile
    if (d < D) {
        int t = r0 + d;
        // highest valid group index touched by this tile
        int tmax = min(r0 + RR, TT) - 1 + (EE - 1);
        if (t <= tmax) {
            int i_lo = max(0, d - (EE - 1));
            int i_hi = min(RR - 1, d);
            float s1 = 0.0f, s2 = 0.0f;
            #pragma unroll 4
            for (int i = i_lo; i <= i_hi; ++i) {
                float v = tile[i * 128 + d];   // == i*129 + (d - i)
                s1 += v;
                s2 = fmaf(v, v, s2);
            }
            atomicAdd(&g_S1[b * LL + t], s1);
            atomicAdd(&g_S2[b * LL + t], s2);
        }
    }
}

// ---------------------------------------------------------------------------
// Kernel 2: var = S2/c - (S1/c)^2, mean over all (b, t), * 0.1
// counts are analytic: c[t] = min(t+1, 128, LL - t)
// ---------------------------------------------------------------------------
__global__ void tcl_finalize_kernel(float* __restrict__ out) {
    __shared__ float red[8];
    float local = 0.0f;
    const int stride = gridDim.x * blockDim.x;
    for (int g = blockIdx.x * blockDim.x + threadIdx.x; g < BB * LL; g += stride) {
        int t = g & (LL - 1);                      // LL is a power of two
        int ci = min(min(t + 1, EE), LL - t);
        float inv_c = 1.0f / (float)ci;
        float s1 = g_S1[g];
        float s2 = g_S2[g];
        float mean = s1 * inv_c;
        local += s2 * inv_c - mean * mean;
    }
    // warp reduce
    #pragma unroll
    for (int o = 16; o; o >>= 1) local += __shfl_down_sync(0xFFFFFFFFu, local, o);
    if ((threadIdx.x & 31) == 0) red[threadIdx.x >> 5] = local;
    __syncthreads();
    if (threadIdx.x < 8) {
        float v = red[threadIdx.x];
        #pragma unroll
        for (int o = 4; o; o >>= 1) v += __shfl_down_sync(0xFFu, v, o);
        if (threadIdx.x == 0) {
            atomicAdd(out, v * (0.1f / ((float)BB * (float)LL)));
        }
    }
}

// ---------------------------------------------------------------------------
extern "C" void kernel_launch(void* const* d_in, const int* in_sizes, int n_in,
                              void* d_out, int out_size) {
    const float* x = (const float*)d_in[0];
    float* out = (float*)d_out;

    // zero scratch + out
    {
        int n = BB * LL;
        tcl_init_kernel<<<(n + 255) / 256, 256>>>(out);
    }
    // main diagonal partial sums
    {
        dim3 grid(TILES, BB);
        tcl_diag_kernel<<<grid, 256>>>(x);
    }
    // finalize
    {
        tcl_finalize_kernel<<<256, 256>>>(out);
    }
}